// round 17
// baseline (speedup 1.0000x reference)
#include <cuda_runtime.h>
#include <cuda_fp16.h>
#include <cstdint>
#include <math.h>

#define H 1024
#define IDIM 4096
#define NE 8
#define T_TOK 8192
#define NSLOT (2 * T_TOK)

// ---------------- device scratch ----------------
__device__ int    g_count[NE];
__device__ int    g_base[NE];
__device__ int    g_tok[NE * T_TOK];
__device__ float  g_wt[NE * T_TOK];
__device__ float  g_probs[T_TOK * NE];
__device__ __half g_h[(size_t)(NSLOT + 128) * IDIM];     // hidden acts (fp16)
__device__ __half g_xh[(size_t)T_TOK * H];               // x in fp16
__device__ __half g_w1h[(size_t)NE * 2 * IDIM * H];      // gate_up_w fp16
__device__ __half g_w2h[(size_t)NE * H * IDIM];          // down_w fp16

// ---------------- helpers ----------------
__device__ __forceinline__ uint32_t h2pack(float a, float b) {
    __half2 h = __floats2half2_rn(a, b);
    return *(uint32_t*)&h;
}
__device__ __forceinline__ uint2 cvt4h(float4 v) {
    return make_uint2(h2pack(v.x, v.y), h2pack(v.z, v.w));
}
__device__ __forceinline__ uint32_t smem_u32(const void* p) {
    uint32_t a;
    asm("{ .reg .u64 t; cvta.to.shared.u64 t, %1; cvt.u32.u64 %0, t; }" : "=r"(a) : "l"(p));
    return a;
}
__device__ __forceinline__ void cp16(uint32_t dst, const void* src) {
    asm volatile("cp.async.cg.shared.global [%0], [%1], 16;" :: "r"(dst), "l"(src));
}
#define CP_COMMIT() asm volatile("cp.async.commit_group;" ::: "memory")
#define CP_WAIT0()  asm volatile("cp.async.wait_group 0;" ::: "memory")

__device__ __forceinline__ void mma_f16(float* d, const unsigned* a, const unsigned* b) {
    asm volatile(
        "mma.sync.aligned.m16n8k16.row.col.f32.f16.f16.f32 "
        "{%0,%1,%2,%3}, {%4,%5,%6,%7}, {%8,%9}, {%0,%1,%2,%3};\n"
        : "+f"(d[0]), "+f"(d[1]), "+f"(d[2]), "+f"(d[3])
        : "r"(a[0]), "r"(a[1]), "r"(a[2]), "r"(a[3]), "r"(b[0]), "r"(b[1]));
}
__device__ __forceinline__ void ldsm_x4(unsigned* r, uint32_t addr) {
    asm volatile("ldmatrix.sync.aligned.m8n8.x4.shared.b16 {%0,%1,%2,%3}, [%4];"
                 : "=r"(r[0]), "=r"(r[1]), "=r"(r[2]), "=r"(r[3]) : "r"(addr));
}

// ---------------- zero / init ----------------
__global__ void zero_out_kernel(float* out, int n) {
    int i = blockIdx.x * blockDim.x + threadIdx.x;
    int stride = gridDim.x * blockDim.x;
    if (i < NE) g_count[i] = 0;
    for (; i < n; i += stride) out[i] = 0.0f;
}

// ---------------- fp32 -> fp16 conversion ----------------
__global__ void cvt_f2h_kernel(const float4* __restrict__ src, uint2* __restrict__ dst,
                               size_t n4) {
    size_t i = (size_t)blockIdx.x * blockDim.x + threadIdx.x;
    size_t stride = (size_t)gridDim.x * blockDim.x;
    for (; i < n4; i += stride) dst[i] = cvt4h(src[i]);
}

// ---------------- gating: logits, softmax, top-2, routing ----------------
__global__ __launch_bounds__(256) void gating_kernel(const float* __restrict__ x,
                                                     const float* __restrict__ gw) {
    __shared__ float sgw[NE * H];
    for (int i = threadIdx.x; i < NE * H; i += blockDim.x) sgw[i] = gw[i];
    __syncthreads();

    int warp = threadIdx.x >> 5, lane = threadIdx.x & 31;
    int t = blockIdx.x * 8 + warp;
    const float* xr = x + (size_t)t * H;

    float acc[NE];
#pragma unroll
    for (int e = 0; e < NE; e++) acc[e] = 0.0f;
    for (int k = lane; k < H; k += 32) {
        float xv = xr[k];
#pragma unroll
        for (int e = 0; e < NE; e++) acc[e] += xv * sgw[e * H + k];
    }
#pragma unroll
    for (int e = 0; e < NE; e++)
#pragma unroll
        for (int off = 16; off; off >>= 1)
            acc[e] += __shfl_xor_sync(0xffffffffu, acc[e], off);

    if (lane == 0) {
        float mx = acc[0];
#pragma unroll
        for (int e = 1; e < NE; e++) mx = fmaxf(mx, acc[e]);
        float p[NE], s = 0.0f;
#pragma unroll
        for (int e = 0; e < NE; e++) { p[e] = expf(acc[e] - mx); s += p[e]; }
        float inv = 1.0f / s;
#pragma unroll
        for (int e = 0; e < NE; e++) { p[e] *= inv; g_probs[t * NE + e] = p[e]; }

        int b0 = 0;
#pragma unroll
        for (int e = 1; e < NE; e++) if (p[e] > p[b0]) b0 = e;
        int b1 = (b0 == 0) ? 1 : 0;
#pragma unroll
        for (int e = 0; e < NE; e++) if (e != b0 && p[e] > p[b1]) b1 = e;

        float d = 1.0f / (p[b0] + p[b1] + 1e-9f);
        int pos0 = atomicAdd(&g_count[b0], 1);
        g_tok[b0 * T_TOK + pos0] = t;
        g_wt[b0 * T_TOK + pos0] = p[b0] * d;
        int pos1 = atomicAdd(&g_count[b1], 1);
        g_tok[b1 * T_TOK + pos1] = t;
        g_wt[b1 * T_TOK + pos1] = p[b1] * d;
    }
}

// ---------------- prefix scan + aux loss ----------------
__global__ void scan_aux_kernel(float* out) {
    __shared__ float red[256];
    __shared__ float imp[NE];
    float s[NE];
#pragma unroll
    for (int e = 0; e < NE; e++) s[e] = 0.0f;
    for (int i = threadIdx.x; i < T_TOK; i += 256)
#pragma unroll
        for (int e = 0; e < NE; e++) s[e] += g_probs[i * NE + e];
    for (int e = 0; e < NE; e++) {
        red[threadIdx.x] = s[e];
        __syncthreads();
        for (int off = 128; off; off >>= 1) {
            if (threadIdx.x < off) red[threadIdx.x] += red[threadIdx.x + off];
            __syncthreads();
        }
        if (threadIdx.x == 0) imp[e] = red[0];
        __syncthreads();
    }
    if (threadIdx.x == 0) {
        int b = 0;
        float aux = 0.0f;
        for (int e = 0; e < NE; e++) {
            g_base[e] = b;
            b += g_count[e];
            float usage = (float)g_count[e] / ((float)(T_TOK * 2) + 1e-9f);
            aux += usage * (imp[e] / (float)T_TOK);
        }
        out[(size_t)T_TOK * H] = fminf(aux * (float)NE * 0.01f, 1.0f);
    }
}

// ---------------- unified GEMM tiling: 128m x 256 B-rows, 64x64 warp tiles ----------------
#define BK 32
#define KS2 40      // half stride per smem row (80B)
#define NSTG 4      // two 64-K pairs
#define BM 128
#define BROWS 256   // B region rows per stage
#define STGH ((BM + BROWS) * KS2)            // 15360 halves / stage
#define G_SMEM (512 + NSTG * STGH * 2)       // 123392 B

// ---------------- GEMM1: h = silu(x@Wg^T) * (x@Wu^T) ----------------
__global__ __launch_bounds__(256, 1) void gemm1_kernel(const __half* __restrict__ xh,
                                                       const __half* __restrict__ w1h) {
    int e = blockIdx.z;
    int cnt = g_count[e];
    int m0 = blockIdx.x * BM;
    if (m0 >= cnt) return;
    int n0 = blockIdx.y * 128;   // 128 gate cols + 128 up cols

    extern __shared__ __align__(16) char smraw[];
    int* stok = (int*)smraw;
    __half* stg = (__half*)(smraw + 512);
    uint32_t stg_b = smem_u32(stg);

    int tid = threadIdx.x, warp = tid >> 5, lane = tid & 31;
    int wm = warp >> 2, wn = warp & 3;   // 2m x 4n

    if (tid < BM) {
        int p = m0 + tid;
        stok[tid] = (p < cnt) ? g_tok[e * T_TOK + p] : 0;
    }
    __syncthreads();

    // cp.async plan: 1536 chunks / stage -> 6 per thread
    const __half* srcb[6];
    uint32_t dsto[6];
#pragma unroll
    for (int t = 0; t < 6; t++) {
        int idx = tid + 256 * t;
        if (idx < 512) {                      // A: 128 rows x 4 chunks
            int r = idx >> 2, c = idx & 3;
            srcb[t] = xh + (size_t)stok[r] * H + c * 8;
            dsto[t] = (r * KS2 + c * 8) * 2;
        } else {                              // B: rows 0-127 gate, 128-255 up
            int j = idx - 512;
            int r = j >> 2, c = j & 3;
            size_t wrow = (r < 128) ? (size_t)(n0 + r) : (size_t)(IDIM + n0 + r - 128);
            srcb[t] = w1h + (size_t)e * 2 * IDIM * H + wrow * H + c * 8;
            dsto[t] = ((BM + r) * KS2 + c * 8) * 2;
        }
    }

    // ldmatrix half-offsets
    uint32_t offA[4], offB[4];
#pragma unroll
    for (int mf = 0; mf < 4; mf++)
        offA[mf] = (uint32_t)((wm * 64 + mf * 16 + (lane & 7) + ((lane >> 3) & 1) * 8) * KS2
                              + ((lane >> 4) & 1) * 8);
#pragma unroll
    for (int p = 0; p < 4; p++)
        offB[p] = (uint32_t)((BM + wn * 64 + p * 16 + (lane & 7) + ((lane >> 4) & 1) * 8) * KS2
                             + ((lane >> 3) & 1) * 8);

    const int NIT = (H / BK) / 2;  // 16
#pragma unroll
    for (int s = 0; s < 2; s++) {
        uint32_t db = stg_b + s * STGH * 2;
#pragma unroll
        for (int t = 0; t < 6; t++) cp16(db + dsto[t], srcb[t] + s * BK);
    }
    CP_COMMIT();

    float acc[4][8][4];
#pragma unroll
    for (int a = 0; a < 4; a++)
#pragma unroll
        for (int b = 0; b < 8; b++)
#pragma unroll
            for (int c = 0; c < 4; c++) acc[a][b][c] = 0.0f;

    for (int it = 0; it < NIT; it++) {
        CP_WAIT0();
        __syncthreads();
        if (it + 1 < NIT) {
            int pp = (it + 1) & 1;
#pragma unroll
            for (int s = 0; s < 2; s++) {
                uint32_t db = stg_b + (2 * pp + s) * STGH * 2;
                int kslab = 2 * (it + 1) + s;
#pragma unroll
                for (int t = 0; t < 6; t++) cp16(db + dsto[t], srcb[t] + kslab * BK);
            }
            CP_COMMIT();
        }
        int cp = it & 1;
#pragma unroll
        for (int s = 0; s < 2; s++) {
            uint32_t stage_b = stg_b + (2 * cp + s) * STGH * 2;
#pragma unroll
            for (int ks = 0; ks < 2; ks++) {
                uint32_t kb = stage_b + ks * 32;
                unsigned a[4][4], b[8][2];
                ldsm_x4(a[0], kb + offA[0] * 2);
                ldsm_x4(a[1], kb + offA[1] * 2);
                ldsm_x4(a[2], kb + offA[2] * 2);
                ldsm_x4(a[3], kb + offA[3] * 2);
                ldsm_x4(&b[0][0], kb + offB[0] * 2);
                ldsm_x4(&b[2][0], kb + offB[1] * 2);
                ldsm_x4(&b[4][0], kb + offB[2] * 2);
                ldsm_x4(&b[6][0], kb + offB[3] * 2);
#pragma unroll
                for (int mf = 0; mf < 4; mf++)
#pragma unroll
                    for (int nf = 0; nf < 8; nf++) mma_f16(acc[mf][nf], a[mf], b[nf]);
            }
        }
    }
    __syncthreads();

    // ---- epilogue ----
    // warps with wn>=2 hold u (cols (wn-2)*64..): stage u fp32 to smem
    int g4 = lane >> 2, tig = lane & 3;
    float* US = (float*)stg;                 // [128][132] fp32
    if (wn >= 2) {
#pragma unroll
        for (int mf = 0; mf < 4; mf++)
#pragma unroll
            for (int nf = 0; nf < 8; nf++)
#pragma unroll
                for (int hh = 0; hh < 2; hh++) {
                    int row = wm * 64 + mf * 16 + g4 + hh * 8;
                    int col = (wn - 2) * 64 + nf * 8 + tig * 2;
                    *(float2*)&US[row * 132 + col] =
                        make_float2(acc[mf][nf][hh * 2 + 0], acc[mf][nf][hh * 2 + 1]);
                }
    }
    __syncthreads();

    // g-warps (wn<2) compute h = silu(g)*u in fp32, stage h fp16
    __half* Hs = stg + 33792;                // [128][136] fp16 (starts at byte 67584)
    if (wn < 2) {
#pragma unroll
        for (int mf = 0; mf < 4; mf++)
#pragma unroll
            for (int nf = 0; nf < 8; nf++)
#pragma unroll
                for (int hh = 0; hh < 2; hh++) {
                    int row = wm * 64 + mf * 16 + g4 + hh * 8;
                    int col = wn * 64 + nf * 8 + tig * 2;
                    float2 uv = *(float2*)&US[row * 132 + col];
                    float gv0 = acc[mf][nf][hh * 2 + 0];
                    float gv1 = acc[mf][nf][hh * 2 + 1];
                    float h0 = gv0 / (1.0f + __expf(-gv0)) * uv.x;
                    float h1 = gv1 / (1.0f + __expf(-gv1)) * uv.y;
                    *(uint32_t*)&Hs[row * 136 + col] = h2pack(h0, h1);
                }
    }
    __syncthreads();

    // copy h tile (128x128 fp16) to g_h
    int mybase = g_base[e];
#pragma unroll
    for (int t = 0; t < 8; t++) {
        int idx = tid + t * 256;
        int r = idx >> 4, c8 = idx & 15;
        if (m0 + r < cnt) {
            uint4 v = *(uint4*)&Hs[r * 136 + c8 * 8];
            *(uint4*)&g_h[(size_t)(mybase + m0 + r) * IDIM + n0 + c8 * 8] = v;
        }
    }
}

// ---------------- GEMM2: out[tok] += w * (h @ W2^T) ----------------
__global__ __launch_bounds__(256, 1) void gemm2_kernel(const __half* __restrict__ w2h,
                                                       float* __restrict__ out) {
    int e = blockIdx.z;
    int cnt = g_count[e];
    int m0 = blockIdx.x * BM;
    if (m0 >= cnt) return;
    int n0 = blockIdx.y * 256;
    int base = g_base[e];

    extern __shared__ __align__(16) char smraw[];
    __half* stg = (__half*)(smraw + 512);
    uint32_t stg_b = smem_u32(stg);

    int tid = threadIdx.x, warp = tid >> 5, lane = tid & 31;
    int wm = warp >> 2, wn = warp & 3;

    const __half* Ab = g_h + (size_t)(base + m0) * IDIM;

    const __half* srcb[6];
    uint32_t dsto[6];
#pragma unroll
    for (int t = 0; t < 6; t++) {
        int idx = tid + 256 * t;
        if (idx < 512) {
            int r = idx >> 2, c = idx & 3;
            srcb[t] = Ab + (size_t)r * IDIM + c * 8;
            dsto[t] = (r * KS2 + c * 8) * 2;
        } else {
            int j = idx - 512;
            int r = j >> 2, c = j & 3;
            srcb[t] = w2h + ((size_t)e * H + n0 + r) * IDIM + c * 8;
            dsto[t] = ((BM + r) * KS2 + c * 8) * 2;
        }
    }

    uint32_t offA[4], offB[4];
#pragma unroll
    for (int mf = 0; mf < 4; mf++)
        offA[mf] = (uint32_t)((wm * 64 + mf * 16 + (lane & 7) + ((lane >> 3) & 1) * 8) * KS2
                              + ((lane >> 4) & 1) * 8);
#pragma unroll
    for (int p = 0; p < 4; p++)
        offB[p] = (uint32_t)((BM + wn * 64 + p * 16 + (lane & 7) + ((lane >> 4) & 1) * 8) * KS2
                             + ((lane >> 3) & 1) * 8);

    const int NIT = (IDIM / BK) / 2;  // 64
#pragma unroll
    for (int s = 0; s < 2; s++) {
        uint32_t db = stg_b + s * STGH * 2;
#pragma unroll
        for (int t = 0; t < 6; t++) cp16(db + dsto[t], srcb[t] + s * BK);
    }
    CP_COMMIT();

    float acc[4][8][4];
#pragma unroll
    for (int a = 0; a < 4; a++)
#pragma unroll
        for (int b = 0; b < 8; b++)
#pragma unroll
            for (int c = 0; c < 4; c++) acc[a][b][c] = 0.0f;

    for (int it = 0; it < NIT; it++) {
        CP_WAIT0();
        __syncthreads();
        if (it + 1 < NIT) {
            int pp = (it + 1) & 1;
#pragma unroll
            for (int s = 0; s < 2; s++) {
                uint32_t db = stg_b + (2 * pp + s) * STGH * 2;
                int kslab = 2 * (it + 1) + s;
#pragma unroll
                for (int t = 0; t < 6; t++) cp16(db + dsto[t], srcb[t] + kslab * BK);
            }
            CP_COMMIT();
        }
        int cp = it & 1;
#pragma unroll
        for (int s = 0; s < 2; s++) {
            uint32_t stage_b = stg_b + (2 * cp + s) * STGH * 2;
#pragma unroll
            for (int ks = 0; ks < 2; ks++) {
                uint32_t kb = stage_b + ks * 32;
                unsigned a[4][4], b[8][2];
                ldsm_x4(a[0], kb + offA[0] * 2);
                ldsm_x4(a[1], kb + offA[1] * 2);
                ldsm_x4(a[2], kb + offA[2] * 2);
                ldsm_x4(a[3], kb + offA[3] * 2);
                ldsm_x4(&b[0][0], kb + offB[0] * 2);
                ldsm_x4(&b[2][0], kb + offB[1] * 2);
                ldsm_x4(&b[4][0], kb + offB[2] * 2);
                ldsm_x4(&b[6][0], kb + offB[3] * 2);
#pragma unroll
                for (int mf = 0; mf < 4; mf++)
#pragma unroll
                    for (int nf = 0; nf < 8; nf++) mma_f16(acc[mf][nf], a[mf], b[nf]);
            }
        }
    }

    // epilogue: weighted scatter-add (exactly 2 adds per out element)
    int g4 = lane >> 2, tig = lane & 3;
#pragma unroll
    for (int mf = 0; mf < 4; mf++) {
#pragma unroll
        for (int half = 0; half < 2; half++) {
            int r = wm * 64 + mf * 16 + g4 + half * 8;
            int gr = m0 + r;
            if (gr < cnt) {
                int tok = g_tok[e * T_TOK + gr];
                float w = g_wt[e * T_TOK + gr];
                float* op = out + (size_t)tok * H + n0 + wn * 64;
#pragma unroll
                for (int nf = 0; nf < 8; nf++) {
                    atomicAdd(op + nf * 8 + tig * 2, w * acc[mf][nf][half * 2 + 0]);
                    atomicAdd(op + nf * 8 + tig * 2 + 1, w * acc[mf][nf][half * 2 + 1]);
                }
            }
        }
    }
}

// ---------------- launch ----------------
extern "C" void kernel_launch(void* const* d_in, const int* in_sizes, int n_in,
                              void* d_out, int out_size) {
    const float* x = (const float*)d_in[0];
    const float* gate_w = (const float*)d_in[1];
    const float* gate_up_w = (const float*)d_in[2];
    const float* down_w = (const float*)d_in[3];
    float* out = (float*)d_out;

    static int attr_done = 0;
    if (!attr_done) {
        cudaFuncSetAttribute(gemm1_kernel, cudaFuncAttributeMaxDynamicSharedMemorySize, G_SMEM);
        cudaFuncSetAttribute(gemm2_kernel, cudaFuncAttributeMaxDynamicSharedMemorySize, G_SMEM);
        attr_done = 1;
    }

    zero_out_kernel<<<4096, 256>>>(out, out_size);

    __half* xh_p;   cudaGetSymbolAddress((void**)&xh_p, g_xh);
    __half* w1h_p;  cudaGetSymbolAddress((void**)&w1h_p, g_w1h);
    __half* w2h_p;  cudaGetSymbolAddress((void**)&w2h_p, g_w2h);
    cvt_f2h_kernel<<<2048, 256>>>((const float4*)x, (uint2*)xh_p, (size_t)T_TOK * H / 4);
    cvt_f2h_kernel<<<8192, 256>>>((const float4*)gate_up_w, (uint2*)w1h_p,
                                  (size_t)NE * 2 * IDIM * H / 4);
    cvt_f2h_kernel<<<4096, 256>>>((const float4*)down_w, (uint2*)w2h_p,
                                  (size_t)NE * H * IDIM / 4);

    gating_kernel<<<T_TOK / 8, 256>>>(x, gate_w);
    scan_aux_kernel<<<1, 256>>>(out);

    dim3 g1(T_TOK / BM, IDIM / 128, NE);   // (64, 32, 8)
    gemm1_kernel<<<g1, 256, G_SMEM>>>(xh_p, w1h_p);

    dim3 g2(T_TOK / BM, H / 256, NE);      // (64, 4, 8)
    gemm2_kernel<<<g2, 256, G_SMEM>>>(w2h_p, out);
}